// round 14
// baseline (speedup 1.0000x reference)
#include <cuda_runtime.h>
#include <cuda_bf16.h>
#include <stdint.h>

#define B_  8
#define H_  8
#define M_  512
#define N_  512
#define DD  64
#define HID 16

#define BM 64
#define BN 64
#define THREADS 128
#define NTILES (N_ / BN)
#define LOG2E 1.44269504088896340736f

// smem word (u32) offsets; rows are 36 words (32 data + 4 pad)
#define W_QHI 0          // [64][36]
#define W_QLO 2304
#define W_KHI 4608       // [64][36]
#define W_KLO 6912
#define W_VTHI 9216      // V^T [64 d][36] (cols = key-pair words, XOR-swizzled)
#define W_VTLO 11520
#define SMEM_WORDS 13824
#define SMEM_BYTES (SMEM_WORDS * 4)   // 55296

typedef unsigned long long ull;

__device__ __forceinline__ ull fma2(ull a, ull b, ull c) {
    ull d; asm("fma.rn.f32x2 %0,%1,%2,%3;" : "=l"(d) : "l"(a), "l"(b), "l"(c)); return d;
}
__device__ __forceinline__ ull pk(float x, float y) {
    ull r; asm("mov.b64 %0,{%1,%2};" : "=l"(r) : "f"(x), "f"(y)); return r;
}
__device__ __forceinline__ void upk(ull a, float& x, float& y) {
    asm("mov.b64 {%0,%1},%2;" : "=f"(x), "=f"(y) : "l"(a));
}
__device__ __forceinline__ ull relu2(ull a) {
    float x, y; upk(a, x, y);
    return pk(fmaxf(x, 0.0f), fmaxf(y, 0.0f));
}
// pack two f32 -> bf16x2 (x in LOW half, matching fragment col-even-in-low)
__device__ __forceinline__ uint32_t cvt2(float x, float y) {
    uint32_t r; asm("cvt.rn.bf16x2.f32 %0, %1, %2;" : "=r"(r) : "f"(y), "f"(x)); return r;
}
__device__ __forceinline__ float lo16f(uint32_t w) { return __uint_as_float(w << 16); }
__device__ __forceinline__ float hi16f(uint32_t w) { return __uint_as_float(w & 0xffff0000u); }

__device__ __forceinline__ uint32_t cvta_smem(const void* p) {
    uint32_t a;
    asm("{ .reg .u64 t; cvta.to.shared.u64 t, %1; cvt.u32.u64 %0, t; }" : "=r"(a) : "l"(p));
    return a;
}

#define LDSM4(r, addr) \
    asm volatile("ldmatrix.sync.aligned.m8n8.x4.shared.b16 {%0,%1,%2,%3}, [%4];" \
        : "=r"((r)[0]), "=r"((r)[1]), "=r"((r)[2]), "=r"((r)[3]) : "r"(addr))

// D += A * B   (m16n8k16 row.col, bf16 in, f32 accum)
__device__ __forceinline__ void mma16816(float* d, const uint32_t* a, uint32_t b0, uint32_t b1) {
    asm volatile(
        "mma.sync.aligned.m16n8k16.row.col.f32.bf16.bf16.f32 "
        "{%0,%1,%2,%3}, {%4,%5,%6,%7}, {%8,%9}, {%0,%1,%2,%3};"
        : "+f"(d[0]), "+f"(d[1]), "+f"(d[2]), "+f"(d[3])
        : "r"(a[0]), "r"(a[1]), "r"(a[2]), "r"(a[3]), "r"(b0), "r"(b1));
}

__global__ __launch_bounds__(THREADS, 4)
void msdpa_mma_kernel(const float* __restrict__ q,
                      const float* __restrict__ k,
                      const float* __restrict__ v,
                      const float* __restrict__ dmat,
                      const float* __restrict__ mixW1,
                      const float* __restrict__ mixb1,
                      const float* __restrict__ mixW2,
                      const float* __restrict__ mixb2,
                      float* __restrict__ out)
{
    extern __shared__ uint32_t sm[];
    uint32_t* Qhi = sm + W_QHI;
    uint32_t* Qlo = sm + W_QLO;
    uint32_t* Khi = sm + W_KHI;
    uint32_t* Klo = sm + W_KLO;
    uint32_t* Vthi = sm + W_VTHI;
    uint32_t* Vtlo = sm + W_VTLO;

    __shared__ __align__(16) float sWp[HID * 8];
    __shared__ float sB2;

    const int tid  = threadIdx.x;
    const int wid  = tid >> 5;     // 0..3
    const int lane = tid & 31;
    const int g    = lane >> 2;
    const int tig  = lane & 3;

    const int b  = blockIdx.z;
    const int h  = blockIdx.y;
    const int m0 = blockIdx.x * BM;

    const float* qb = q + ((size_t)(b * H_ + h) * M_ + m0) * DD;
    const float* kb = k + (size_t)(b * H_ + h) * N_ * DD;
    const float* vb = v + (size_t)(b * H_ + h) * N_ * DD;

    if (tid < HID) {
        const float scale = 0.125f;
        float a = mixW1[(h * 2 + 0) * HID + tid] * scale;
        float c = mixW1[(h * 2 + 1) * HID + tid];
        float e = mixb1[h * HID + tid];
        float w = mixW2[h * HID + tid] * LOG2E;
        float* wp = sWp + tid * 8;
        wp[0] = a; wp[1] = a; wp[2] = c; wp[3] = c;
        wp[4] = e; wp[5] = e; wp[6] = w; wp[7] = w;
    }
    if (tid == 0) sB2 = mixb2[h] * LOG2E;

    // ---- stage Q (hi/lo split) once: [64 rows][32 words], stride 36 ----
    {
        int row = tid >> 1;            // 0..63
        int c0  = (tid & 1) * 16;
        const float* qr = qb + row * DD + (tid & 1) * 32;
        #pragma unroll
        for (int i = 0; i < 8; i++) {
            float4 f = ((const float4*)qr)[i];
            uint32_t h0 = cvt2(f.x, f.y);
            uint32_t l0 = cvt2(f.x - lo16f(h0), f.y - hi16f(h0));
            uint32_t h1 = cvt2(f.z, f.w);
            uint32_t l1 = cvt2(f.z - lo16f(h1), f.w - hi16f(h1));
            int w = row * 36 + c0 + i * 2;
            *(uint2*)(Qhi + w) = make_uint2(h0, h1);
            *(uint2*)(Qlo + w) = make_uint2(l0, l1);
        }
    }

    float Od[8][4];
    #pragma unroll
    for (int d = 0; d < 8; d++)
        #pragma unroll
        for (int e = 0; e < 4; e++) Od[d][e] = 0.0f;
    float rs0 = 0.0f, rs1 = 0.0f;

    __syncthreads();
    const ull b2p = pk(sB2, sB2);

    // ldmatrix per-lane address offsets (in words)
    const int l = lane;
    const int q_off  = (wid * 16 + (l & 7) + 8 * ((l >> 3) & 1)) * 36 + 4 * (l >> 4);
    const int kv_row = (l & 7) + 8 * (l >> 4);
    const int k_off  = kv_row * 36 + 4 * ((l >> 3) & 1);
    const int xb     = ((l >> 3) & 1) ^ ((l >> 4) & 1);
    const int v_off  = kv_row * 36 + 4 * xb;

    const uint32_t qhi_b  = cvta_smem(Qhi);
    const uint32_t qlo_b  = cvta_smem(Qlo);
    const uint32_t khi_b  = cvta_smem(Khi);
    const uint32_t klo_b  = cvta_smem(Klo);
    const uint32_t vthi_b = cvta_smem(Vthi);
    const uint32_t vtlo_b = cvta_smem(Vtlo);

    const float* dm0 = dmat + ((size_t)b * M_ + m0 + wid * 16 + g) * N_;

    for (int t = 0; t < NTILES; t++) {
        // ---- stage K tile [64][64] hi/lo (2 passes of the 256-thread map) ----
        #pragma unroll
        for (int s = 0; s < 2; s++) {
            int st  = tid + s * 128;
            int key = st >> 2;
            int c0  = (st & 3) * 8;
            const float* kr = kb + (size_t)(t * BN + key) * DD + (st & 3) * 16;
            #pragma unroll
            for (int i = 0; i < 4; i++) {
                float4 f = ((const float4*)kr)[i];
                uint32_t h0 = cvt2(f.x, f.y);
                uint32_t l0 = cvt2(f.x - lo16f(h0), f.y - hi16f(h0));
                uint32_t h1 = cvt2(f.z, f.w);
                uint32_t l1 = cvt2(f.z - lo16f(h1), f.w - hi16f(h1));
                int w = key * 36 + c0 + i * 2;
                *(uint2*)(Khi + w) = make_uint2(h0, h1);
                *(uint2*)(Klo + w) = make_uint2(l0, l1);
            }
        }
        // ---- stage V^T tile (2 passes), col XOR-swizzled by (d>>3)<<2 ----
        #pragma unroll
        for (int s = 0; s < 2; s++) {
            int st = tid + s * 128;
            int kp = st >> 3;
            int a  = st & 7;
            int d0 = a * 8;
            const float* v0 = vb + (size_t)(t * BN + 2 * kp) * DD + d0;
            const float* v1 = v0 + DD;
            float4 f0a = ((const float4*)v0)[0], f0b = ((const float4*)v0)[1];
            float4 f1a = ((const float4*)v1)[0], f1b = ((const float4*)v1)[1];
            float e0[8] = {f0a.x, f0a.y, f0a.z, f0a.w, f0b.x, f0b.y, f0b.z, f0b.w};
            float e1[8] = {f1a.x, f1a.y, f1a.z, f1a.w, f1b.x, f1b.y, f1b.z, f1b.w};
            int colp = kp ^ (a << 2);
            #pragma unroll
            for (int i = 0; i < 8; i++) {
                uint32_t hw = cvt2(e0[i], e1[i]);   // lo: key 2kp, hi: key 2kp+1
                uint32_t lw = cvt2(e0[i] - lo16f(hw), e1[i] - hi16f(hw));
                Vthi[(d0 + i) * 36 + colp] = hw;
                Vtlo[(d0 + i) * 36 + colp] = lw;
            }
        }
        __syncthreads();

        // ---- S = Q K^T via 3-product split mma; frags via ldmatrix.x4 ----
        float S[8][4];
        #pragma unroll
        for (int n = 0; n < 8; n++)
            #pragma unroll
            for (int e = 0; e < 4; e++) S[n][e] = 0.0f;

        #pragma unroll
        for (int kc = 0; kc < 4; kc++) {
            uint32_t qh[4], ql[4];
            LDSM4(qh, qhi_b + 4 * (q_off + 8 * kc));
            LDSM4(ql, qlo_b + 4 * (q_off + 8 * kc));
            #pragma unroll
            for (int nb = 0; nb < 4; nb++) {   // n-block pair (2nb, 2nb+1)
                uint32_t kh[4], kl[4];
                uint32_t koff = 4 * (k_off + 576 * nb + 8 * kc);
                LDSM4(kh, khi_b + koff);
                LDSM4(kl, klo_b + koff);
                mma16816(S[2 * nb],     qh, kh[0], kh[1]);
                mma16816(S[2 * nb],     qh, kl[0], kl[1]);
                mma16816(S[2 * nb],     ql, kh[0], kh[1]);
                mma16816(S[2 * nb + 1], qh, kh[2], kh[3]);
                mma16816(S[2 * nb + 1], qh, kl[2], kl[3]);
                mma16816(S[2 * nb + 1], ql, kh[2], kh[3]);
            }
        }

        // ---- MLP + exp2 (unnormalized); P fragments built in registers ----
        uint32_t PhiA[8], PhiB[8], PloA[8], PloB[8];
        #pragma unroll
        for (int n = 0; n < 8; n++) {
            int col = t * BN + n * 8 + tig * 2;
            float2 dA = *(const float2*)(dm0 + col);
            float2 dB = *(const float2*)(dm0 + 8 * N_ + col);
            ull ms01 = pk(S[n][0], S[n][1]);
            ull ms23 = pk(S[n][2], S[n][3]);
            ull dm01 = pk(dA.x, dA.y);
            ull dm23 = pk(dB.x, dB.y);
            ull a01 = b2p, a23 = b2p;
            #pragma unroll
            for (int f = 0; f < HID; f++) {
                const ull w1s = *(const ull*)(sWp + f * 8 + 0);
                const ull w1d = *(const ull*)(sWp + f * 8 + 2);
                const ull bb  = *(const ull*)(sWp + f * 8 + 4);
                const ull w2  = *(const ull*)(sWp + f * 8 + 6);
                a01 = fma2(w2, relu2(fma2(w1s, ms01, fma2(w1d, dm01, bb))), a01);
                a23 = fma2(w2, relu2(fma2(w1s, ms23, fma2(w1d, dm23, bb))), a23);
            }
            float p0, p1, p2, p3;
            upk(a01, p0, p1); upk(a23, p2, p3);
            p0 = exp2f(p0); p1 = exp2f(p1); p2 = exp2f(p2); p3 = exp2f(p3);
            rs0 += p0 + p1;
            rs1 += p2 + p3;
            uint32_t hA = cvt2(p0, p1);
            PhiA[n] = hA;
            PloA[n] = cvt2(p0 - lo16f(hA), p1 - hi16f(hA));
            uint32_t hB = cvt2(p2, p3);
            PhiB[n] = hB;
            PloB[n] = cvt2(p2 - lo16f(hB), p3 - hi16f(hB));
        }

        // ---- O += P V via 3-product split mma; V frags via ldmatrix.x4 ----
        #pragma unroll
        for (int kc = 0; kc < 4; kc++) {
            uint32_t ah[4] = {PhiA[2 * kc], PhiB[2 * kc], PhiA[2 * kc + 1], PhiB[2 * kc + 1]};
            uint32_t al[4] = {PloA[2 * kc], PloB[2 * kc], PloA[2 * kc + 1], PloB[2 * kc + 1]};
            #pragma unroll
            for (int hh = 0; hh < 4; hh++) {   // dt pair (2hh, 2hh+1)
                uint32_t vh[4], vl[4];
                uint32_t voff = 4 * (v_off + 576 * hh + 8 * (kc ^ hh));
                LDSM4(vh, vthi_b + voff);
                LDSM4(vl, vtlo_b + voff);
                mma16816(Od[2 * hh],     ah, vh[0], vh[1]);
                mma16816(Od[2 * hh],     ah, vl[0], vl[1]);
                mma16816(Od[2 * hh],     al, vh[0], vh[1]);
                mma16816(Od[2 * hh + 1], ah, vh[2], vh[3]);
                mma16816(Od[2 * hh + 1], ah, vl[2], vl[3]);
                mma16816(Od[2 * hh + 1], al, vh[2], vh[3]);
            }
        }
        __syncthreads();
    }

    // ---- epilogue: quad-reduce row sums, normalize, store ----
    const unsigned FULL = 0xffffffffu;
    rs0 += __shfl_xor_sync(FULL, rs0, 1);
    rs0 += __shfl_xor_sync(FULL, rs0, 2);
    rs1 += __shfl_xor_sync(FULL, rs1, 1);
    rs1 += __shfl_xor_sync(FULL, rs1, 2);
    float i0 = 1.0f / rs0;
    float i1 = 1.0f / rs1;

    float* o0 = out + ((size_t)(b * H_ + h) * M_ + m0 + wid * 16 + g) * DD;
    float* o1 = o0 + 8 * DD;
    #pragma unroll
    for (int dt = 0; dt < 8; dt++) {
        *(float2*)(o0 + dt * 8 + tig * 2) = make_float2(Od[dt][0] * i0, Od[dt][1] * i0);
        *(float2*)(o1 + dt * 8 + tig * 2) = make_float2(Od[dt][2] * i1, Od[dt][3] * i1);
    }
}

extern "C" void kernel_launch(void* const* d_in, const int* in_sizes, int n_in,
                              void* d_out, int out_size)
{
    const float* q     = (const float*)d_in[0];
    const float* k     = (const float*)d_in[1];
    const float* v     = (const float*)d_in[2];
    const float* dmat  = (const float*)d_in[3];
    const float* mixW1 = (const float*)d_in[4];
    const float* mixb1 = (const float*)d_in[5];
    const float* mixW2 = (const float*)d_in[6];
    const float* mixb2 = (const float*)d_in[7];
    float* out = (float*)d_out;

    cudaFuncSetAttribute(msdpa_mma_kernel,
                         cudaFuncAttributeMaxDynamicSharedMemorySize, SMEM_BYTES);

    dim3 grid(M_ / BM, H_, B_);   // (8, 8, 8)
    msdpa_mma_kernel<<<grid, THREADS, SMEM_BYTES>>>(q, k, v, dmat,
                                                    mixW1, mixb1, mixW2, mixb2, out);
}

// round 15
// speedup vs baseline: 1.0231x; 1.0231x over previous
#include <cuda_runtime.h>
#include <cuda_bf16.h>
#include <stdint.h>

#define B_  8
#define H_  8
#define M_  512
#define N_  512
#define DD  64
#define HID 16

#define BM 128
#define BN 64
#define THREADS 256
#define NTILES (N_ / BN)
#define LOG2E 1.44269504088896340736f

// smem word (u32) offsets; rows are 36 words (32 data + 4 pad)
#define W_QHI 0          // [128][36]
#define W_QLO 4608
#define W_KHI 9216       // [64][36]
#define W_KLO 11520
#define W_VTHI 13824     // V^T [64 d][36] (cols = key-pair words, XOR-swizzled)
#define W_VTLO 16128
#define SMEM_WORDS 18432
#define SMEM_BYTES (SMEM_WORDS * 4)

typedef unsigned long long ull;

__device__ __forceinline__ ull fma2(ull a, ull b, ull c) {
    ull d; asm("fma.rn.f32x2 %0,%1,%2,%3;" : "=l"(d) : "l"(a), "l"(b), "l"(c)); return d;
}
__device__ __forceinline__ ull pk(float x, float y) {
    ull r; asm("mov.b64 %0,{%1,%2};" : "=l"(r) : "f"(x), "f"(y)); return r;
}
__device__ __forceinline__ void upk(ull a, float& x, float& y) {
    asm("mov.b64 {%0,%1},%2;" : "=f"(x), "=f"(y) : "l"(a));
}
__device__ __forceinline__ ull relu2(ull a) {
    float x, y; upk(a, x, y);
    return pk(fmaxf(x, 0.0f), fmaxf(y, 0.0f));
}
// pack two f32 -> bf16x2 (x in LOW half, matching fragment col-even-in-low)
__device__ __forceinline__ uint32_t cvt2(float x, float y) {
    uint32_t r; asm("cvt.rn.bf16x2.f32 %0, %1, %2;" : "=r"(r) : "f"(y), "f"(x)); return r;
}
__device__ __forceinline__ float lo16f(uint32_t w) { return __uint_as_float(w << 16); }
__device__ __forceinline__ float hi16f(uint32_t w) { return __uint_as_float(w & 0xffff0000u); }

__device__ __forceinline__ uint32_t cvta_smem(const void* p) {
    uint32_t a;
    asm("{ .reg .u64 t; cvta.to.shared.u64 t, %1; cvt.u32.u64 %0, t; }" : "=r"(a) : "l"(p));
    return a;
}

#define LDSM4(r, addr) \
    asm volatile("ldmatrix.sync.aligned.m8n8.x4.shared.b16 {%0,%1,%2,%3}, [%4];" \
        : "=r"((r)[0]), "=r"((r)[1]), "=r"((r)[2]), "=r"((r)[3]) : "r"(addr))

// D += A * B   (m16n8k16 row.col, bf16 in, f32 accum)
__device__ __forceinline__ void mma16816(float* d, const uint32_t* a, uint32_t b0, uint32_t b1) {
    asm volatile(
        "mma.sync.aligned.m16n8k16.row.col.f32.bf16.bf16.f32 "
        "{%0,%1,%2,%3}, {%4,%5,%6,%7}, {%8,%9}, {%0,%1,%2,%3};"
        : "+f"(d[0]), "+f"(d[1]), "+f"(d[2]), "+f"(d[3])
        : "r"(a[0]), "r"(a[1]), "r"(a[2]), "r"(a[3]), "r"(b0), "r"(b1));
}

__global__ __launch_bounds__(THREADS, 2)
void msdpa_mma_kernel(const float* __restrict__ q,
                      const float* __restrict__ k,
                      const float* __restrict__ v,
                      const float* __restrict__ dmat,
                      const float* __restrict__ mixW1,
                      const float* __restrict__ mixb1,
                      const float* __restrict__ mixW2,
                      const float* __restrict__ mixb2,
                      float* __restrict__ out)
{
    extern __shared__ uint32_t sm[];
    uint32_t* Qhi = sm + W_QHI;
    uint32_t* Qlo = sm + W_QLO;
    uint32_t* Khi = sm + W_KHI;
    uint32_t* Klo = sm + W_KLO;
    uint32_t* Vthi = sm + W_VTHI;
    uint32_t* Vtlo = sm + W_VTLO;

    __shared__ __align__(16) float sWp[HID * 8];
    __shared__ float sB2;

    const int tid  = threadIdx.x;
    const int wid  = tid >> 5;
    const int lane = tid & 31;
    const int g    = lane >> 2;
    const int tig  = lane & 3;

    const int b  = blockIdx.z;
    const int h  = blockIdx.y;
    const int m0 = blockIdx.x * BM;

    const float* qb = q + ((size_t)(b * H_ + h) * M_ + m0) * DD;
    const float* kb = k + (size_t)(b * H_ + h) * N_ * DD;
    const float* vb = v + (size_t)(b * H_ + h) * N_ * DD;

    if (tid < HID) {
        const float scale = 0.125f;
        float a = mixW1[(h * 2 + 0) * HID + tid] * scale;
        float c = mixW1[(h * 2 + 1) * HID + tid];
        float e = mixb1[h * HID + tid];
        float w = mixW2[h * HID + tid] * LOG2E;
        float* wp = sWp + tid * 8;
        wp[0] = a; wp[1] = a; wp[2] = c; wp[3] = c;
        wp[4] = e; wp[5] = e; wp[6] = w; wp[7] = w;
    }
    if (tid == 0) sB2 = mixb2[h] * LOG2E;

    // ---- stage Q (hi/lo split) once: [128 rows][32 words], stride 36 ----
    {
        int row = tid >> 1;
        int c0  = (tid & 1) * 16;
        const float* qr = qb + row * DD + (tid & 1) * 32;
        #pragma unroll
        for (int i = 0; i < 8; i++) {
            float4 f = ((const float4*)qr)[i];
            uint32_t h0 = cvt2(f.x, f.y);
            uint32_t l0 = cvt2(f.x - lo16f(h0), f.y - hi16f(h0));
            uint32_t h1 = cvt2(f.z, f.w);
            uint32_t l1 = cvt2(f.z - lo16f(h1), f.w - hi16f(h1));
            int w = row * 36 + c0 + i * 2;
            *(uint2*)(Qhi + w) = make_uint2(h0, h1);
            *(uint2*)(Qlo + w) = make_uint2(l0, l1);
        }
    }

    float Od[8][4];
    #pragma unroll
    for (int d = 0; d < 8; d++)
        #pragma unroll
        for (int e = 0; e < 4; e++) Od[d][e] = 0.0f;
    float rs0 = 0.0f, rs1 = 0.0f;

    __syncthreads();
    const ull b2p = pk(sB2, sB2);

    // ldmatrix per-lane address offsets (in words)
    const int l = lane;
    const int q_off  = (wid * 16 + (l & 7) + 8 * ((l >> 3) & 1)) * 36 + 4 * (l >> 4);
    const int kv_row = (l & 7) + 8 * (l >> 4);
    const int k_off  = kv_row * 36 + 4 * ((l >> 3) & 1);
    const int xb     = ((l >> 3) & 1) ^ ((l >> 4) & 1);
    const int v_off  = kv_row * 36 + 4 * xb;

    const uint32_t qhi_b  = cvta_smem(Qhi);
    const uint32_t qlo_b  = cvta_smem(Qlo);
    const uint32_t khi_b  = cvta_smem(Khi);
    const uint32_t klo_b  = cvta_smem(Klo);
    const uint32_t vthi_b = cvta_smem(Vthi);
    const uint32_t vtlo_b = cvta_smem(Vtlo);

    const float* dm0 = dmat + ((size_t)b * M_ + m0 + wid * 16 + g) * N_;

    for (int t = 0; t < NTILES; t++) {
        // ---- stage K tile [64][64] hi/lo ----
        {
            int key = tid >> 2;
            int c0  = (tid & 3) * 8;
            const float* kr = kb + (size_t)(t * BN + key) * DD + (tid & 3) * 16;
            #pragma unroll
            for (int i = 0; i < 4; i++) {
                float4 f = ((const float4*)kr)[i];
                uint32_t h0 = cvt2(f.x, f.y);
                uint32_t l0 = cvt2(f.x - lo16f(h0), f.y - hi16f(h0));
                uint32_t h1 = cvt2(f.z, f.w);
                uint32_t l1 = cvt2(f.z - lo16f(h1), f.w - hi16f(h1));
                int w = key * 36 + c0 + i * 2;
                *(uint2*)(Khi + w) = make_uint2(h0, h1);
                *(uint2*)(Klo + w) = make_uint2(l0, l1);
            }
        }
        // ---- stage V^T tile: Vt[d][keypair-word], col XOR-swizzled by (d>>3)<<2 ----
        {
            int kp = tid >> 3;
            int a  = tid & 7;
            int d0 = a * 8;
            const float* v0 = vb + (size_t)(t * BN + 2 * kp) * DD + d0;
            const float* v1 = v0 + DD;
            float4 f0a = ((const float4*)v0)[0], f0b = ((const float4*)v0)[1];
            float4 f1a = ((const float4*)v1)[0], f1b = ((const float4*)v1)[1];
            float e0[8] = {f0a.x, f0a.y, f0a.z, f0a.w, f0b.x, f0b.y, f0b.z, f0b.w};
            float e1[8] = {f1a.x, f1a.y, f1a.z, f1a.w, f1b.x, f1b.y, f1b.z, f1b.w};
            int colp = kp ^ (a << 2);
            #pragma unroll
            for (int i = 0; i < 8; i++) {
                uint32_t hw = cvt2(e0[i], e1[i]);   // lo: key 2kp, hi: key 2kp+1
                uint32_t lw = cvt2(e0[i] - lo16f(hw), e1[i] - hi16f(hw));
                Vthi[(d0 + i) * 36 + colp] = hw;
                Vtlo[(d0 + i) * 36 + colp] = lw;
            }
        }
        __syncthreads();

        // ---- S = Q K^T via 3-product split mma; frags via ldmatrix.x4 ----
        float S[8][4];
        #pragma unroll
        for (int n = 0; n < 8; n++)
            #pragma unroll
            for (int e = 0; e < 4; e++) S[n][e] = 0.0f;

        #pragma unroll
        for (int kc = 0; kc < 4; kc++) {
            uint32_t qh[4], ql[4];
            LDSM4(qh, qhi_b + 4 * (q_off + 8 * kc));
            LDSM4(ql, qlo_b + 4 * (q_off + 8 * kc));
            #pragma unroll
            for (int nb = 0; nb < 4; nb++) {   // n-block pair (2nb, 2nb+1)
                uint32_t kh[4], kl[4];
                uint32_t koff = 4 * (k_off + 576 * nb + 8 * kc);
                LDSM4(kh, khi_b + koff);
                LDSM4(kl, klo_b + koff);
                mma16816(S[2 * nb],     qh, kh[0], kh[1]);
                mma16816(S[2 * nb],     qh, kl[0], kl[1]);
                mma16816(S[2 * nb],     ql, kh[0], kh[1]);
                mma16816(S[2 * nb + 1], qh, kh[2], kh[3]);
                mma16816(S[2 * nb + 1], qh, kl[2], kl[3]);
                mma16816(S[2 * nb + 1], ql, kh[2], kh[3]);
            }
        }

        // ---- MLP + exp2 (unnormalized), n chunked by 2, weights via 2x LDS.128 ----
        uint32_t PhiA[8], PhiB[8], PloA[8], PloB[8];
        #pragma unroll
        for (int n0 = 0; n0 < 8; n0 += 2) {
            ull ms01[2], ms23[2], dm01[2], dm23[2], a01[2], a23[2];
            #pragma unroll
            for (int e = 0; e < 2; e++) {
                int n = n0 + e;
                int col = t * BN + n * 8 + tig * 2;
                float2 dA = *(const float2*)(dm0 + col);
                float2 dB = *(const float2*)(dm0 + 8 * N_ + col);
                ms01[e] = pk(S[n][0], S[n][1]);
                ms23[e] = pk(S[n][2], S[n][3]);
                dm01[e] = pk(dA.x, dA.y);
                dm23[e] = pk(dB.x, dB.y);
                a01[e] = b2p; a23[e] = b2p;
            }
            #pragma unroll
            for (int f = 0; f < HID; f++) {
                ull wv[4];
                *(uint4*)(&wv[0]) = *(const uint4*)(sWp + f * 8);
                *(uint4*)(&wv[2]) = *(const uint4*)(sWp + f * 8 + 4);
                const ull w1s = wv[0];
                const ull w1d = wv[1];
                const ull bb  = wv[2];
                const ull w2  = wv[3];
                #pragma unroll
                for (int e = 0; e < 2; e++) {
                    a01[e] = fma2(w2, relu2(fma2(w1s, ms01[e], fma2(w1d, dm01[e], bb))), a01[e]);
                    a23[e] = fma2(w2, relu2(fma2(w1s, ms23[e], fma2(w1d, dm23[e], bb))), a23[e]);
                }
            }
            #pragma unroll
            for (int e = 0; e < 2; e++) {
                int n = n0 + e;
                float p0, p1, p2, p3;
                upk(a01[e], p0, p1); upk(a23[e], p2, p3);
                p0 = exp2f(p0); p1 = exp2f(p1); p2 = exp2f(p2); p3 = exp2f(p3);
                rs0 += p0 + p1;
                rs1 += p2 + p3;
                uint32_t hA = cvt2(p0, p1);
                PhiA[n] = hA;
                PloA[n] = cvt2(p0 - lo16f(hA), p1 - hi16f(hA));
                uint32_t hB = cvt2(p2, p3);
                PhiB[n] = hB;
                PloB[n] = cvt2(p2 - lo16f(hB), p3 - hi16f(hB));
            }
        }

        // ---- O += P V via 3-product split mma; V frags via ldmatrix.x4 ----
        #pragma unroll
        for (int kc = 0; kc < 4; kc++) {
            uint32_t ah[4] = {PhiA[2 * kc], PhiB[2 * kc], PhiA[2 * kc + 1], PhiB[2 * kc + 1]};
            uint32_t al[4] = {PloA[2 * kc], PloB[2 * kc], PloA[2 * kc + 1], PloB[2 * kc + 1]};
            #pragma unroll
            for (int hh = 0; hh < 4; hh++) {   // dt pair (2hh, 2hh+1)
                uint32_t vh[4], vl[4];
                uint32_t voff = 4 * (v_off + 576 * hh + 8 * (kc ^ hh));
                LDSM4(vh, vthi_b + voff);
                LDSM4(vl, vtlo_b + voff);
                mma16816(Od[2 * hh],     ah, vh[0], vh[1]);
                mma16816(Od[2 * hh],     ah, vl[0], vl[1]);
                mma16816(Od[2 * hh],     al, vh[0], vh[1]);
                mma16816(Od[2 * hh + 1], ah, vh[2], vh[3]);
                mma16816(Od[2 * hh + 1], ah, vl[2], vl[3]);
                mma16816(Od[2 * hh + 1], al, vh[2], vh[3]);
            }
        }
        __syncthreads();
    }

    // ---- epilogue: quad-reduce row sums, normalize, store ----
    const unsigned FULL = 0xffffffffu;
    rs0 += __shfl_xor_sync(FULL, rs0, 1);
    rs0 += __shfl_xor_sync(FULL, rs0, 2);
    rs1 += __shfl_xor_sync(FULL, rs1, 1);
    rs1 += __shfl_xor_sync(FULL, rs1, 2);
    float i0 = 1.0f / rs0;
    float i1 = 1.0f / rs1;

    float* o0 = out + ((size_t)(b * H_ + h) * M_ + m0 + wid * 16 + g) * DD;
    float* o1 = o0 + 8 * DD;
    #pragma unroll
    for (int dt = 0; dt < 8; dt++) {
        *(float2*)(o0 + dt * 8 + tig * 2) = make_float2(Od[dt][0] * i0, Od[dt][1] * i0);
        *(float2*)(o1 + dt * 8 + tig * 2) = make_float2(Od[dt][2] * i1, Od[dt][3] * i1);
    }
}

extern "C" void kernel_launch(void* const* d_in, const int* in_sizes, int n_in,
                              void* d_out, int out_size)
{
    const float* q     = (const float*)d_in[0];
    const float* k     = (const float*)d_in[1];
    const float* v     = (const float*)d_in[2];
    const float* dmat  = (const float*)d_in[3];
    const float* mixW1 = (const float*)d_in[4];
    const float* mixb1 = (const float*)d_in[5];
    const float* mixW2 = (const float*)d_in[6];
    const float* mixb2 = (const float*)d_in[7];
    float* out = (float*)d_out;

    cudaFuncSetAttribute(msdpa_mma_kernel,
                         cudaFuncAttributeMaxDynamicSharedMemorySize, SMEM_BYTES);

    dim3 grid(M_ / BM, H_, B_);   // (4, 8, 8)
    msdpa_mma_kernel<<<grid, THREADS, SMEM_BYTES>>>(q, k, v, dmat,
                                                    mixW1, mixb1, mixW2, mixb2, out);
}

// round 16
// speedup vs baseline: 1.0625x; 1.0385x over previous
#include <cuda_runtime.h>
#include <cuda_bf16.h>
#include <stdint.h>

#define B_  8
#define H_  8
#define M_  512
#define N_  512
#define DD  64
#define HID 16

#define BM 128
#define BN 64
#define THREADS 256
#define NTILES (N_ / BN)
#define LOG2E 1.44269504088896340736f

// smem word (u32) offsets; rows are 36 words (32 data + 4 pad)
#define W_QHI 0          // [128][36]
#define W_QLO 4608
#define W_KHI 9216       // [64][36]
#define W_KLO 11520
#define W_VTHI 13824     // V^T [64 d][36] (cols = key-pair words, XOR-swizzled)
#define W_VTLO 16128
#define SMEM_WORDS 18432
#define SMEM_BYTES (SMEM_WORDS * 4)

typedef unsigned long long ull;

__device__ __forceinline__ ull fma2(ull a, ull b, ull c) {
    ull d; asm("fma.rn.f32x2 %0,%1,%2,%3;" : "=l"(d) : "l"(a), "l"(b), "l"(c)); return d;
}
__device__ __forceinline__ ull pk(float x, float y) {
    ull r; asm("mov.b64 %0,{%1,%2};" : "=l"(r) : "f"(x), "f"(y)); return r;
}
__device__ __forceinline__ void upk(ull a, float& x, float& y) {
    asm("mov.b64 {%0,%1},%2;" : "=f"(x), "=f"(y) : "l"(a));
}
__device__ __forceinline__ ull relu2(ull a) {
    float x, y; upk(a, x, y);
    return pk(fmaxf(x, 0.0f), fmaxf(y, 0.0f));
}
__device__ __forceinline__ float ex2(float x) {
    float r; asm("ex2.approx.f32 %0, %1;" : "=f"(r) : "f"(x)); return r;
}
// pack two f32 -> bf16x2 (x in LOW half, matching fragment col-even-in-low)
__device__ __forceinline__ uint32_t cvt2(float x, float y) {
    uint32_t r; asm("cvt.rn.bf16x2.f32 %0, %1, %2;" : "=r"(r) : "f"(y), "f"(x)); return r;
}
__device__ __forceinline__ float lo16f(uint32_t w) { return __uint_as_float(w << 16); }
__device__ __forceinline__ float hi16f(uint32_t w) { return __uint_as_float(w & 0xffff0000u); }

__device__ __forceinline__ uint32_t cvta_smem(const void* p) {
    uint32_t a;
    asm("{ .reg .u64 t; cvta.to.shared.u64 t, %1; cvt.u32.u64 %0, t; }" : "=r"(a) : "l"(p));
    return a;
}

#define LDSM4(r, addr) \
    asm volatile("ldmatrix.sync.aligned.m8n8.x4.shared.b16 {%0,%1,%2,%3}, [%4];" \
        : "=r"((r)[0]), "=r"((r)[1]), "=r"((r)[2]), "=r"((r)[3]) : "r"(addr))

// D += A * B   (m16n8k16 row.col, bf16 in, f32 accum)
__device__ __forceinline__ void mma16816(float* d, const uint32_t* a, uint32_t b0, uint32_t b1) {
    asm volatile(
        "mma.sync.aligned.m16n8k16.row.col.f32.bf16.bf16.f32 "
        "{%0,%1,%2,%3}, {%4,%5,%6,%7}, {%8,%9}, {%0,%1,%2,%3};"
        : "+f"(d[0]), "+f"(d[1]), "+f"(d[2]), "+f"(d[3])
        : "r"(a[0]), "r"(a[1]), "r"(a[2]), "r"(a[3]), "r"(b0), "r"(b1));
}

__global__ __launch_bounds__(THREADS, 2)
void msdpa_mma_kernel(const float* __restrict__ q,
                      const float* __restrict__ k,
                      const float* __restrict__ v,
                      const float* __restrict__ dmat,
                      const float* __restrict__ mixW1,
                      const float* __restrict__ mixb1,
                      const float* __restrict__ mixW2,
                      const float* __restrict__ mixb2,
                      float* __restrict__ out)
{
    extern __shared__ uint32_t sm[];
    uint32_t* Qhi = sm + W_QHI;
    uint32_t* Qlo = sm + W_QLO;
    uint32_t* Khi = sm + W_KHI;
    uint32_t* Klo = sm + W_KLO;
    uint32_t* Vthi = sm + W_VTHI;
    uint32_t* Vtlo = sm + W_VTLO;

    __shared__ __align__(16) float sWp[HID * 8];
    __shared__ float sB2;

    const int tid  = threadIdx.x;
    const int wid  = tid >> 5;
    const int lane = tid & 31;
    const int g    = lane >> 2;
    const int tig  = lane & 3;

    const int b  = blockIdx.z;
    const int h  = blockIdx.y;
    const int m0 = blockIdx.x * BM;

    const float* qb = q + ((size_t)(b * H_ + h) * M_ + m0) * DD;
    const float* kb = k + (size_t)(b * H_ + h) * N_ * DD;
    const float* vb = v + (size_t)(b * H_ + h) * N_ * DD;

    if (tid < HID) {
        const float scale = 0.125f;
        float a = mixW1[(h * 2 + 0) * HID + tid] * scale;
        float c = mixW1[(h * 2 + 1) * HID + tid];
        float e = mixb1[h * HID + tid];
        float w = mixW2[h * HID + tid] * LOG2E;
        float* wp = sWp + tid * 8;
        wp[0] = a; wp[1] = a; wp[2] = c; wp[3] = c;
        wp[4] = e; wp[5] = e; wp[6] = w; wp[7] = w;
    }
    if (tid == 0) sB2 = mixb2[h] * LOG2E;

    // ---- stage Q (hi/lo split) once: [128 rows][32 words], stride 36 ----
    {
        int row = tid >> 1;
        int c0  = (tid & 1) * 16;
        const float* qr = qb + row * DD + (tid & 1) * 32;
        #pragma unroll
        for (int i = 0; i < 8; i++) {
            float4 f = ((const float4*)qr)[i];
            uint32_t h0 = cvt2(f.x, f.y);
            uint32_t l0 = cvt2(f.x - lo16f(h0), f.y - hi16f(h0));
            uint32_t h1 = cvt2(f.z, f.w);
            uint32_t l1 = cvt2(f.z - lo16f(h1), f.w - hi16f(h1));
            int w = row * 36 + c0 + i * 2;
            *(uint2*)(Qhi + w) = make_uint2(h0, h1);
            *(uint2*)(Qlo + w) = make_uint2(l0, l1);
        }
    }

    float Od[8][4];
    #pragma unroll
    for (int d = 0; d < 8; d++)
        #pragma unroll
        for (int e = 0; e < 4; e++) Od[d][e] = 0.0f;
    float rs0 = 0.0f, rs1 = 0.0f;

    __syncthreads();
    const ull b2p = pk(sB2, sB2);

    // ldmatrix per-lane address offsets (in words)
    const int l = lane;
    const int q_off  = (wid * 16 + (l & 7) + 8 * ((l >> 3) & 1)) * 36 + 4 * (l >> 4);
    const int kv_row = (l & 7) + 8 * (l >> 4);
    const int k_off  = kv_row * 36 + 4 * ((l >> 3) & 1);
    const int xb     = ((l >> 3) & 1) ^ ((l >> 4) & 1);
    const int v_off  = kv_row * 36 + 4 * xb;

    const uint32_t qhi_b  = cvta_smem(Qhi);
    const uint32_t qlo_b  = cvta_smem(Qlo);
    const uint32_t khi_b  = cvta_smem(Khi);
    const uint32_t klo_b  = cvta_smem(Klo);
    const uint32_t vthi_b = cvta_smem(Vthi);
    const uint32_t vtlo_b = cvta_smem(Vtlo);

    const float* dm0 = dmat + ((size_t)b * M_ + m0 + wid * 16 + g) * N_;

    for (int t = 0; t < NTILES; t++) {
        // ---- stage K tile [64][64] hi/lo ----
        {
            int key = tid >> 2;
            int c0  = (tid & 3) * 8;
            const float* kr = kb + (size_t)(t * BN + key) * DD + (tid & 3) * 16;
            #pragma unroll
            for (int i = 0; i < 4; i++) {
                float4 f = ((const float4*)kr)[i];
                uint32_t h0 = cvt2(f.x, f.y);
                uint32_t l0 = cvt2(f.x - lo16f(h0), f.y - hi16f(h0));
                uint32_t h1 = cvt2(f.z, f.w);
                uint32_t l1 = cvt2(f.z - lo16f(h1), f.w - hi16f(h1));
                int w = key * 36 + c0 + i * 2;
                *(uint2*)(Khi + w) = make_uint2(h0, h1);
                *(uint2*)(Klo + w) = make_uint2(l0, l1);
            }
        }
        // ---- stage V^T tile: Vt[d][keypair-word], col XOR-swizzled by (d>>3)<<2 ----
        {
            int kp = tid >> 3;
            int a  = tid & 7;
            int d0 = a * 8;
            const float* v0 = vb + (size_t)(t * BN + 2 * kp) * DD + d0;
            const float* v1 = v0 + DD;
            float4 f0a = ((const float4*)v0)[0], f0b = ((const float4*)v0)[1];
            float4 f1a = ((const float4*)v1)[0], f1b = ((const float4*)v1)[1];
            float e0[8] = {f0a.x, f0a.y, f0a.z, f0a.w, f0b.x, f0b.y, f0b.z, f0b.w};
            float e1[8] = {f1a.x, f1a.y, f1a.z, f1a.w, f1b.x, f1b.y, f1b.z, f1b.w};
            int colp = kp ^ (a << 2);
            #pragma unroll
            for (int i = 0; i < 8; i++) {
                uint32_t hw = cvt2(e0[i], e1[i]);   // lo: key 2kp, hi: key 2kp+1
                uint32_t lw = cvt2(e0[i] - lo16f(hw), e1[i] - hi16f(hw));
                Vthi[(d0 + i) * 36 + colp] = hw;
                Vtlo[(d0 + i) * 36 + colp] = lw;
            }
        }
        __syncthreads();

        // ---- prefetch dmat for n=0 while MMAs run ----
        const float* dmt = dm0 + t * BN + tig * 2;
        float2 dA_pf = *(const float2*)(dmt);
        float2 dB_pf = *(const float2*)(dmt + 8 * N_);

        // ---- S = Q K^T via 3-product split mma; frags via ldmatrix.x4 ----
        float S[8][4];
        #pragma unroll
        for (int n = 0; n < 8; n++)
            #pragma unroll
            for (int e = 0; e < 4; e++) S[n][e] = 0.0f;

        #pragma unroll
        for (int kc = 0; kc < 4; kc++) {
            uint32_t qh[4], ql[4];
            LDSM4(qh, qhi_b + 4 * (q_off + 8 * kc));
            LDSM4(ql, qlo_b + 4 * (q_off + 8 * kc));
            #pragma unroll
            for (int nb = 0; nb < 4; nb++) {   // n-block pair (2nb, 2nb+1)
                uint32_t kh[4], kl[4];
                uint32_t koff = 4 * (k_off + 576 * nb + 8 * kc);
                LDSM4(kh, khi_b + koff);
                LDSM4(kl, klo_b + koff);
                mma16816(S[2 * nb],     qh, kh[0], kh[1]);
                mma16816(S[2 * nb],     qh, kl[0], kl[1]);
                mma16816(S[2 * nb],     ql, kh[0], kh[1]);
                mma16816(S[2 * nb + 1], qh, kh[2], kh[3]);
                mma16816(S[2 * nb + 1], qh, kl[2], kl[3]);
                mma16816(S[2 * nb + 1], ql, kh[2], kh[3]);
            }
        }

        // ---- MLP + exp2 (unnormalized); dmat software-pipelined one n ahead ----
        uint32_t PhiA[8], PhiB[8], PloA[8], PloB[8];
        #pragma unroll
        for (int n = 0; n < 8; n++) {
            float2 dA = dA_pf;
            float2 dB = dB_pf;
            if (n < 7) {
                dA_pf = *(const float2*)(dmt + (n + 1) * 8);
                dB_pf = *(const float2*)(dmt + 8 * N_ + (n + 1) * 8);
            }
            ull ms01 = pk(S[n][0], S[n][1]);
            ull ms23 = pk(S[n][2], S[n][3]);
            ull dm01 = pk(dA.x, dA.y);
            ull dm23 = pk(dB.x, dB.y);
            ull a01 = b2p, a23 = b2p;
            #pragma unroll
            for (int f = 0; f < HID; f++) {
                const ull w1s = *(const ull*)(sWp + f * 8 + 0);
                const ull w1d = *(const ull*)(sWp + f * 8 + 2);
                const ull bb  = *(const ull*)(sWp + f * 8 + 4);
                const ull w2  = *(const ull*)(sWp + f * 8 + 6);
                a01 = fma2(w2, relu2(fma2(w1s, ms01, fma2(w1d, dm01, bb))), a01);
                a23 = fma2(w2, relu2(fma2(w1s, ms23, fma2(w1d, dm23, bb))), a23);
            }
            float p0, p1, p2, p3;
            upk(a01, p0, p1); upk(a23, p2, p3);
            p0 = ex2(p0); p1 = ex2(p1); p2 = ex2(p2); p3 = ex2(p3);
            rs0 += p0 + p1;
            rs1 += p2 + p3;
            uint32_t hA = cvt2(p0, p1);
            PhiA[n] = hA;
            PloA[n] = cvt2(p0 - lo16f(hA), p1 - hi16f(hA));
            uint32_t hB = cvt2(p2, p3);
            PhiB[n] = hB;
            PloB[n] = cvt2(p2 - lo16f(hB), p3 - hi16f(hB));
        }

        // ---- O += P V via 3-product split mma; V frags via ldmatrix.x4 ----
        #pragma unroll
        for (int kc = 0; kc < 4; kc++) {
            uint32_t ah[4] = {PhiA[2 * kc], PhiB[2 * kc], PhiA[2 * kc + 1], PhiB[2 * kc + 1]};
            uint32_t al[4] = {PloA[2 * kc], PloB[2 * kc], PloA[2 * kc + 1], PloB[2 * kc + 1]};
            #pragma unroll
            for (int hh = 0; hh < 4; hh++) {   // dt pair (2hh, 2hh+1)
                uint32_t vh[4], vl[4];
                uint32_t voff = 4 * (v_off + 576 * hh + 8 * (kc ^ hh));
                LDSM4(vh, vthi_b + voff);
                LDSM4(vl, vtlo_b + voff);
                mma16816(Od[2 * hh],     ah, vh[0], vh[1]);
                mma16816(Od[2 * hh],     ah, vl[0], vl[1]);
                mma16816(Od[2 * hh],     al, vh[0], vh[1]);
                mma16816(Od[2 * hh + 1], ah, vh[2], vh[3]);
                mma16816(Od[2 * hh + 1], ah, vl[2], vl[3]);
                mma16816(Od[2 * hh + 1], al, vh[2], vh[3]);
            }
        }
        __syncthreads();
    }

    // ---- epilogue: quad-reduce row sums, normalize, store ----
    const unsigned FULL = 0xffffffffu;
    rs0 += __shfl_xor_sync(FULL, rs0, 1);
    rs0 += __shfl_xor_sync(FULL, rs0, 2);
    rs1 += __shfl_xor_sync(FULL, rs1, 1);
    rs1 += __shfl_xor_sync(FULL, rs1, 2);
    float i0 = 1.0f / rs0;
    float i1 = 1.0f / rs1;

    float* o0 = out + ((size_t)(b * H_ + h) * M_ + m0 + wid * 16 + g) * DD;
    float* o1 = o0 + 8 * DD;
    #pragma unroll
    for (int dt = 0; dt < 8; dt++) {
        *(float2*)(o0 + dt * 8 + tig * 2) = make_float2(Od[dt][0] * i0, Od[dt][1] * i0);
        *(float2*)(o1 + dt * 8 + tig * 2) = make_float2(Od[dt][2] * i1, Od[dt][3] * i1);
    }
}

extern "C" void kernel_launch(void* const* d_in, const int* in_sizes, int n_in,
                              void* d_out, int out_size)
{
    const float* q     = (const float*)d_in[0];
    const float* k     = (const float*)d_in[1];
    const float* v     = (const float*)d_in[2];
    const float* dmat  = (const float*)d_in[3];
    const float* mixW1 = (const float*)d_in[4];
    const float* mixb1 = (const float*)d_in[5];
    const float* mixW2 = (const float*)d_in[6];
    const float* mixb2 = (const float*)d_in[7];
    float* out = (float*)d_out;

    cudaFuncSetAttribute(msdpa_mma_kernel,
                         cudaFuncAttributeMaxDynamicSharedMemorySize, SMEM_BYTES);

    dim3 grid(M_ / BM, H_, B_);   // (4, 8, 8)
    msdpa_mma_kernel<<<grid, THREADS, SMEM_BYTES>>>(q, k, v, dmat,
                                                    mixW1, mixb1, mixW2, mixb2, out);
}

// round 17
// speedup vs baseline: 1.1549x; 1.0870x over previous
#include <cuda_runtime.h>
#include <cuda_fp16.h>
#include <stdint.h>

#define B_  8
#define H_  8
#define M_  512
#define N_  512
#define DD  64
#define HID 16

#define BM 128
#define BN 64
#define THREADS 256
#define NTILES (N_ / BN)
#define LOG2E 1.44269504088896340736f
#define PBIAS 10.0f   // p' = p * 2^-10; cancels in normalization

// smem word (u32) offsets; rows are 36 words (32 data + 4 pad)
#define W_QHI 0          // [128][36] fp16x2 (hi part of split Q)
#define W_QLO 4608       // [128][36] fp16x2 (lo residual)
#define W_K   9216       // [64][36]  fp16x2 (single-precision-path K)
#define W_VT  11520      // V^T [64 d][36] fp16x2, col pair XOR-swizzled
#define SMEM_WORDS 13824
#define SMEM_BYTES (SMEM_WORDS * 4)   // 55296

typedef unsigned long long ull;

__device__ __forceinline__ ull fma2(ull a, ull b, ull c) {
    ull d; asm("fma.rn.f32x2 %0,%1,%2,%3;" : "=l"(d) : "l"(a), "l"(b), "l"(c)); return d;
}
__device__ __forceinline__ ull pk(float x, float y) {
    ull r; asm("mov.b64 %0,{%1,%2};" : "=l"(r) : "f"(x), "f"(y)); return r;
}
__device__ __forceinline__ void upk(ull a, float& x, float& y) {
    asm("mov.b64 {%0,%1},%2;" : "=f"(x), "=f"(y) : "l"(a));
}
__device__ __forceinline__ ull relu2(ull a) {
    float x, y; upk(a, x, y);
    return pk(fmaxf(x, 0.0f), fmaxf(y, 0.0f));
}
__device__ __forceinline__ float ex2(float x) {
    float r; asm("ex2.approx.f32 %0, %1;" : "=f"(r) : "f"(x)); return r;
}
// pack two f32 -> f16x2, x in LOW half (matches fragment col-even-in-low)
__device__ __forceinline__ uint32_t cvth2(float x, float y) {
    __half2 hp = __floats2half2_rn(x, y);   // .x (low) = x
    return *reinterpret_cast<uint32_t*>(&hp);
}
__device__ __forceinline__ float lo16h(uint32_t w) {
    __half2 hp = *reinterpret_cast<__half2*>(&w);
    return __half2float(__low2half(hp));
}
__device__ __forceinline__ float hi16h(uint32_t w) {
    __half2 hp = *reinterpret_cast<__half2*>(&w);
    return __half2float(__high2half(hp));
}

__device__ __forceinline__ uint32_t cvta_smem(const void* p) {
    uint32_t a;
    asm("{ .reg .u64 t; cvta.to.shared.u64 t, %1; cvt.u32.u64 %0, t; }" : "=r"(a) : "l"(p));
    return a;
}

#define LDSM4(r, addr) \
    asm volatile("ldmatrix.sync.aligned.m8n8.x4.shared.b16 {%0,%1,%2,%3}, [%4];" \
        : "=r"((r)[0]), "=r"((r)[1]), "=r"((r)[2]), "=r"((r)[3]) : "r"(addr))

// D += A * B   (m16n8k16 row.col, f16 in, f32 accum)
__device__ __forceinline__ void mma16816(float* d, const uint32_t* a, uint32_t b0, uint32_t b1) {
    asm volatile(
        "mma.sync.aligned.m16n8k16.row.col.f32.f16.f16.f32 "
        "{%0,%1,%2,%3}, {%4,%5,%6,%7}, {%8,%9}, {%0,%1,%2,%3};"
        : "+f"(d[0]), "+f"(d[1]), "+f"(d[2]), "+f"(d[3])
        : "r"(a[0]), "r"(a[1]), "r"(a[2]), "r"(a[3]), "r"(b0), "r"(b1));
}

__global__ __launch_bounds__(THREADS, 2)
void msdpa_mma_kernel(const float* __restrict__ q,
                      const float* __restrict__ k,
                      const float* __restrict__ v,
                      const float* __restrict__ dmat,
                      const float* __restrict__ mixW1,
                      const float* __restrict__ mixb1,
                      const float* __restrict__ mixW2,
                      const float* __restrict__ mixb2,
                      float* __restrict__ out)
{
    extern __shared__ uint32_t sm[];
    uint32_t* Qhi = sm + W_QHI;
    uint32_t* Qlo = sm + W_QLO;
    uint32_t* Ks  = sm + W_K;
    uint32_t* Vt  = sm + W_VT;

    __shared__ __align__(16) float sWp[HID * 8];
    __shared__ float sB2;

    const int tid  = threadIdx.x;
    const int wid  = tid >> 5;
    const int lane = tid & 31;
    const int g    = lane >> 2;
    const int tig  = lane & 3;

    const int b  = blockIdx.z;
    const int h  = blockIdx.y;
    const int m0 = blockIdx.x * BM;

    const float* qb = q + ((size_t)(b * H_ + h) * M_ + m0) * DD;
    const float* kb = k + (size_t)(b * H_ + h) * N_ * DD;
    const float* vb = v + (size_t)(b * H_ + h) * N_ * DD;

    if (tid < HID) {
        const float scale = 0.125f;
        float a = mixW1[(h * 2 + 0) * HID + tid] * scale;
        float c = mixW1[(h * 2 + 1) * HID + tid];
        float e = mixb1[h * HID + tid];
        float w = mixW2[h * HID + tid] * LOG2E;
        float* wp = sWp + tid * 8;
        wp[0] = a; wp[1] = a; wp[2] = c; wp[3] = c;
        wp[4] = e; wp[5] = e; wp[6] = w; wp[7] = w;
    }
    if (tid == 0) sB2 = mixb2[h] * LOG2E - PBIAS;

    // ---- stage Q (fp16 hi/lo split) once: [128 rows][32 words], stride 36 ----
    {
        int row = tid >> 1;
        int c0  = (tid & 1) * 16;
        const float* qr = qb + row * DD + (tid & 1) * 32;
        #pragma unroll
        for (int i = 0; i < 8; i++) {
            float4 f = ((const float4*)qr)[i];
            uint32_t h0 = cvth2(f.x, f.y);
            uint32_t l0 = cvth2(f.x - lo16h(h0), f.y - hi16h(h0));
            uint32_t h1 = cvth2(f.z, f.w);
            uint32_t l1 = cvth2(f.z - lo16h(h1), f.w - hi16h(h1));
            int w = row * 36 + c0 + i * 2;
            *(uint2*)(Qhi + w) = make_uint2(h0, h1);
            *(uint2*)(Qlo + w) = make_uint2(l0, l1);
        }
    }

    float Od[8][4];
    #pragma unroll
    for (int d = 0; d < 8; d++)
        #pragma unroll
        for (int e = 0; e < 4; e++) Od[d][e] = 0.0f;
    float rs0 = 0.0f, rs1 = 0.0f;

    __syncthreads();
    const ull b2p = pk(sB2, sB2);

    // ldmatrix per-lane address offsets (in words)
    const int l = lane;
    const int q_off  = (wid * 16 + (l & 7) + 8 * ((l >> 3) & 1)) * 36 + 4 * (l >> 4);
    const int kv_row = (l & 7) + 8 * (l >> 4);
    const int k_off  = kv_row * 36 + 4 * ((l >> 3) & 1);
    const int xb     = ((l >> 3) & 1) ^ ((l >> 4) & 1);
    const int v_off  = kv_row * 36 + 4 * xb;

    const uint32_t qhi_b = cvta_smem(Qhi);
    const uint32_t qlo_b = cvta_smem(Qlo);
    const uint32_t k_b   = cvta_smem(Ks);
    const uint32_t vt_b  = cvta_smem(Vt);

    const float* dm0 = dmat + ((size_t)b * M_ + m0 + wid * 16 + g) * N_;

    for (int t = 0; t < NTILES; t++) {
        // ---- stage K tile [64][64] fp16 single ----
        {
            int key = tid >> 2;
            int c0  = (tid & 3) * 8;
            const float* kr = kb + (size_t)(t * BN + key) * DD + (tid & 3) * 16;
            #pragma unroll
            for (int i = 0; i < 4; i++) {
                float4 f = ((const float4*)kr)[i];
                uint32_t k0 = cvth2(f.x, f.y);
                uint32_t k1 = cvth2(f.z, f.w);
                *(uint2*)(Ks + key * 36 + c0 + i * 2) = make_uint2(k0, k1);
            }
        }
        // ---- stage V^T tile fp16 single: Vt[d][keypair-word], col XOR-swizzled ----
        {
            int kp = tid >> 3;
            int a  = tid & 7;
            int d0 = a * 8;
            const float* v0 = vb + (size_t)(t * BN + 2 * kp) * DD + d0;
            const float* v1 = v0 + DD;
            float4 f0a = ((const float4*)v0)[0], f0b = ((const float4*)v0)[1];
            float4 f1a = ((const float4*)v1)[0], f1b = ((const float4*)v1)[1];
            float e0[8] = {f0a.x, f0a.y, f0a.z, f0a.w, f0b.x, f0b.y, f0b.z, f0b.w};
            float e1[8] = {f1a.x, f1a.y, f1a.z, f1a.w, f1b.x, f1b.y, f1b.z, f1b.w};
            int colp = kp ^ (a << 2);
            #pragma unroll
            for (int i = 0; i < 8; i++)
                Vt[(d0 + i) * 36 + colp] = cvth2(e0[i], e1[i]);   // lo: key 2kp, hi: 2kp+1
        }
        __syncthreads();

        // ---- prefetch dmat for n=0 while MMAs run ----
        const float* dmt = dm0 + t * BN + tig * 2;
        float2 dA_pf = *(const float2*)(dmt);
        float2 dB_pf = *(const float2*)(dmt + 8 * N_);

        // ---- S = Q K^T : 2-product split (Qhi,Qlo) x single K ----
        float S[8][4];
        #pragma unroll
        for (int n = 0; n < 8; n++)
            #pragma unroll
            for (int e = 0; e < 4; e++) S[n][e] = 0.0f;

        #pragma unroll
        for (int kc = 0; kc < 4; kc++) {
            uint32_t qh[4], ql[4];
            LDSM4(qh, qhi_b + 4 * (q_off + 8 * kc));
            LDSM4(ql, qlo_b + 4 * (q_off + 8 * kc));
            #pragma unroll
            for (int nb = 0; nb < 4; nb++) {   // n-block pair (2nb, 2nb+1)
                uint32_t kk[4];
                LDSM4(kk, k_b + 4 * (k_off + 576 * nb + 8 * kc));
                mma16816(S[2 * nb],     qh, kk[0], kk[1]);
                mma16816(S[2 * nb],     ql, kk[0], kk[1]);
                mma16816(S[2 * nb + 1], qh, kk[2], kk[3]);
                mma16816(S[2 * nb + 1], ql, kk[2], kk[3]);
            }
        }

        // ---- MLP + exp2 (unnormalized, 2^-PBIAS scaled); P split fp16 in regs ----
        uint32_t PhiA[8], PhiB[8], PloA[8], PloB[8];
        #pragma unroll
        for (int n = 0; n < 8; n++) {
            float2 dA = dA_pf;
            float2 dB = dB_pf;
            if (n < 7) {
                dA_pf = *(const float2*)(dmt + (n + 1) * 8);
                dB_pf = *(const float2*)(dmt + 8 * N_ + (n + 1) * 8);
            }
            ull ms01 = pk(S[n][0], S[n][1]);
            ull ms23 = pk(S[n][2], S[n][3]);
            ull dm01 = pk(dA.x, dA.y);
            ull dm23 = pk(dB.x, dB.y);
            ull a01 = b2p, a23 = b2p;
            #pragma unroll
            for (int f = 0; f < HID; f++) {
                const ull w1s = *(const ull*)(sWp + f * 8 + 0);
                const ull w1d = *(const ull*)(sWp + f * 8 + 2);
                const ull bb  = *(const ull*)(sWp + f * 8 + 4);
                const ull w2  = *(const ull*)(sWp + f * 8 + 6);
                a01 = fma2(w2, relu2(fma2(w1s, ms01, fma2(w1d, dm01, bb))), a01);
                a23 = fma2(w2, relu2(fma2(w1s, ms23, fma2(w1d, dm23, bb))), a23);
            }
            float p0, p1, p2, p3;
            upk(a01, p0, p1); upk(a23, p2, p3);
            p0 = ex2(p0); p1 = ex2(p1); p2 = ex2(p2); p3 = ex2(p3);
            rs0 += p0 + p1;
            rs1 += p2 + p3;
            uint32_t hA = cvth2(p0, p1);
            PhiA[n] = hA;
            PloA[n] = cvth2(p0 - lo16h(hA), p1 - hi16h(hA));
            uint32_t hB = cvth2(p2, p3);
            PhiB[n] = hB;
            PloB[n] = cvth2(p2 - lo16h(hB), p3 - hi16h(hB));
        }

        // ---- O += P V : 2-product split (Phi,Plo) x single V ----
        #pragma unroll
        for (int kc = 0; kc < 4; kc++) {
            uint32_t ah[4] = {PhiA[2 * kc], PhiB[2 * kc], PhiA[2 * kc + 1], PhiB[2 * kc + 1]};
            uint32_t al[4] = {PloA[2 * kc], PloB[2 * kc], PloA[2 * kc + 1], PloB[2 * kc + 1]};
            #pragma unroll
            for (int hh = 0; hh < 4; hh++) {   // dt pair (2hh, 2hh+1)
                uint32_t vv[4];
                LDSM4(vv, vt_b + 4 * (v_off + 576 * hh + 8 * (kc ^ hh)));
                mma16816(Od[2 * hh],     ah, vv[0], vv[1]);
                mma16816(Od[2 * hh],     al, vv[0], vv[1]);
                mma16816(Od[2 * hh + 1], ah, vv[2], vv[3]);
                mma16816(Od[2 * hh + 1], al, vv[2], vv[3]);
            }
        }
        __syncthreads();
    }

    // ---- epilogue: quad-reduce row sums, normalize, store ----
    const unsigned FULL = 0xffffffffu;
    rs0 += __shfl_xor_sync(FULL, rs0, 1);
    rs0 += __shfl_xor_sync(FULL, rs0, 2);
    rs1 += __shfl_xor_sync(FULL, rs1, 1);
    rs1 += __shfl_xor_sync(FULL, rs1, 2);
    float i0 = 1.0f / rs0;
    float i1 = 1.0f / rs1;

    float* o0 = out + ((size_t)(b * H_ + h) * M_ + m0 + wid * 16 + g) * DD;
    float* o1 = o0 + 8 * DD;
    #pragma unroll
    for (int dt = 0; dt < 8; dt++) {
        *(float2*)(o0 + dt * 8 + tig * 2) = make_float2(Od[dt][0] * i0, Od[dt][1] * i0);
        *(float2*)(o1 + dt * 8 + tig * 2) = make_float2(Od[dt][2] * i1, Od[dt][3] * i1);
    }
}

extern "C" void kernel_launch(void* const* d_in, const int* in_sizes, int n_in,
                              void* d_out, int out_size)
{
    const float* q     = (const float*)d_in[0];
    const float* k     = (const float*)d_in[1];
    const float* v     = (const float*)d_in[2];
    const float* dmat  = (const float*)d_in[3];
    const float* mixW1 = (const float*)d_in[4];
    const float* mixb1 = (const float*)d_in[5];
    const float* mixW2 = (const float*)d_in[6];
    const float* mixb2 = (const float*)d_in[7];
    float* out = (float*)d_out;

    cudaFuncSetAttribute(msdpa_mma_kernel,
                         cudaFuncAttributeMaxDynamicSharedMemorySize, SMEM_BYTES);

    dim3 grid(M_ / BM, H_, B_);   // (4, 8, 8)
    msdpa_mma_kernel<<<grid, THREADS, SMEM_BYTES>>>(q, k, v, dmat,
                                                    mixW1, mixb1, mixW2, mixb2, out);
}